// round 8
// baseline (speedup 1.0000x reference)
#include <cuda_runtime.h>
#include <cstdint>

// Wilson-Cowan, N=2^20, 100 serial steps.
// R8: occupancy round. R7 ran at 77% of its ~100-cyc/warp-step two-pipe floor
//     with only 6.92 warps/SMSP (grid-limited by 8 elems/thread). Now:
//     4 elems/thread (2 packed pairs) -> 2048 blocks stream through 8
//     resident blocks/SM. Pair 0 always tanh (MUFU); pair 1 dithers
//     2-of-5 steps on the MUFU-free exp path (FMA/ALU) -> FMA ~52 cyc,
//     MUFU ~51 cyc per warp-step, balanced.
//     Exp path reuses the tanh-path y: s = -2*log2(e)*y (saves 6 const regs).

typedef unsigned long long u64;

__device__ __forceinline__ u64 pack2(float lo, float hi) {
    u64 r; asm("mov.b64 %0, {%1, %2};" : "=l"(r) : "f"(lo), "f"(hi)); return r;
}
__device__ __forceinline__ void unpack2(float& lo, float& hi, u64 v) {
    asm("mov.b64 {%0, %1}, %2;" : "=f"(lo), "=f"(hi) : "l"(v));
}
__device__ __forceinline__ u64 fma2(u64 a, u64 b, u64 c) {
    u64 d; asm("fma.rn.f32x2 %0, %1, %2, %3;" : "=l"(d) : "l"(a), "l"(b), "l"(c)); return d;
}
__device__ __forceinline__ u64 add2(u64 a, u64 b) {
    u64 d; asm("add.rn.f32x2 %0, %1, %2;" : "=l"(d) : "l"(a), "l"(b)); return d;
}
__device__ __forceinline__ u64 mul2(u64 a, u64 b) {
    u64 d; asm("mul.rn.f32x2 %0, %1, %2;" : "=l"(d) : "l"(a), "l"(b)); return d;
}
__device__ __forceinline__ float tanhf_a(float x) {
    float r; asm("tanh.approx.f32 %0, %1;" : "=f"(r) : "f"(x)); return r;
}

#define SIGN2 0x8000000080000000ULL

__global__ __launch_bounds__(128, 8)
void wilson_cowan_kernel(const float4* __restrict__ E0,
                         const float4* __restrict__ I0,
                         const float4* __restrict__ IextE,
                         const float4* __restrict__ IextI,
                         const int*    __restrict__ steps_ptr,
                         float* __restrict__ out,
                         int n, int n4, int out_size)
{
    int i = blockIdx.x * blockDim.x + threadIdx.x;

    if (blockIdx.x == 0 && threadIdx.x == 0) {
        for (int k = 2 * n; k < out_size; ++k) out[k] = 0.0f;
    }
    if (i >= n4) return;

    const int steps = steps_ptr ? __ldg(steps_ptr) : 100;

    float4 e4  = E0[i];
    float4 i4  = I0[i];
    float4 xe4 = IextE[i];
    float4 xi4 = IextI[i];

    u64 E2[2]  = { pack2(e4.x, e4.y), pack2(e4.z, e4.w) };
    u64 I2[2]  = { pack2(i4.x, i4.y), pack2(i4.z, i4.w) };
    u64 cE2[2] = { pack2(0.5f*(xe4.x-4.0f), 0.5f*(xe4.y-4.0f)),
                   pack2(0.5f*(xe4.z-4.0f), 0.5f*(xe4.w-4.0f)) };
    u64 cI2[2] = { pack2(0.5f*(xi4.x-4.0f), 0.5f*(xi4.y-4.0f)),
                   pack2(0.5f*(xi4.z-4.0f), 0.5f*(xi4.w-4.0f)) };

    // y = 0.5*(input-4); tanh path: E' = 0.99E + 0.005(1+tanh(y))
    // exp path: s = -2*log2(e)*y; sigma = 1/(1+2^s); E' = 0.99E + 0.01*sigma
    const u64 AEE = pack2( 6.0f,  6.0f);
    const u64 AEI = pack2(-2.0f, -2.0f);
    const u64 AIE = pack2( 6.5f,  6.5f);
    const u64 AII = pack2(-5.5f, -5.5f);
    const u64 ME  = pack2(0.99f, 0.99f);
    const u64 MI  = pack2(0.98f, 0.98f);
    const u64 BE  = pack2(0.005f, 0.005f);        // 0.5*kE
    const u64 C01 = pack2(0.01f, 0.01f);          // 0.5*kI == kE
    const u64 KI  = pack2(0.02f, 0.02f);          // kI
    const u64 N2L = pack2(-2.8853900817779268f, -2.8853900817779268f); // -2*log2e
    const u64 MAG  = pack2(12582912.0f, 12582912.0f);   // 1.5*2^23
    const u64 NEG1 = pack2(-1.0f, -1.0f);
    const u64 ONE  = pack2( 1.0f,  1.0f);
    const u64 TWO  = pack2( 2.0f,  2.0f);
    const u64 A1 = pack2(0.69314718f, 0.69314718f);
    const u64 A2 = pack2(0.24022651f, 0.24022651f);
    const u64 A3 = pack2(0.05550411f, 0.05550411f);
    const u64 A4 = pack2(0.00961813f, 0.00961813f);

    auto tanh_step = [&](int p) {
        u64 yE = fma2(AEE, E2[p], fma2(AEI, I2[p], cE2[p]));
        u64 yI = fma2(AIE, E2[p], fma2(AII, I2[p], cI2[p]));
        float a, b, c, d;
        unpack2(a, b, yE);
        unpack2(c, d, yI);
        u64 tE = pack2(tanhf_a(a), tanhf_a(b));
        u64 tI = pack2(tanhf_a(c), tanhf_a(d));
        E2[p] = fma2(BE,  tE, fma2(ME, E2[p], BE));
        I2[p] = fma2(C01, tI, fma2(MI, I2[p], C01));
    };

    // packed 2^s: magic-add range reduction + deg-4 Taylor + exponent splice
    auto exp2_2 = [&](u64 s2) -> u64 {
        u64 m2 = add2(s2, MAG);            // low bits hold rint(s)
        u64 d2 = fma2(MAG, NEG1, m2);      // float(rint(s)), exact
        u64 f2 = fma2(d2, NEG1, s2);       // f in [-0.5, 0.5]
        u64 p  = fma2(A4, f2, A3);
        p = fma2(p, f2, A2);
        p = fma2(p, f2, A1);
        p = fma2(p, f2, ONE);
        float mlo, mhi, plo, phi;
        unpack2(mlo, mhi, m2);
        unpack2(plo, phi, p);
        int zlo = __float_as_int(plo) + (__float_as_int(mlo) << 23);
        int zhi = __float_as_int(phi) + (__float_as_int(mhi) << 23);
        return pack2(__int_as_float(zlo), __int_as_float(zhi));
    };

    auto exp_step = [&](int p) {
        u64 yE = fma2(AEE, E2[p], fma2(AEI, I2[p], cE2[p]));
        u64 yI = fma2(AIE, E2[p], fma2(AII, I2[p], cI2[p]));
        u64 sE = mul2(N2L, yE);            // in [-11.6, 11.6]
        u64 sI = mul2(N2L, yI);            // in [-12.3, 22.4]
        u64 zE = exp2_2(sE);
        u64 zI = exp2_2(sI);
        u64 wE = add2(zE, ONE);
        u64 wI = add2(zI, ONE);
        u64 P  = mul2(wE, wI);             // <= ~1.6e10, normal
        float plo, phi;
        unpack2(plo, phi, P);
        u64 r = pack2(__int_as_float(0x7EF311C3 - __float_as_int(plo)),
                      __int_as_float(0x7EF311C3 - __float_as_int(phi)));
        r = mul2(r, fma2(P, r ^ SIGN2, TWO));   // Newton 1
        r = mul2(r, fma2(P, r ^ SIGN2, TWO));   // Newton 2: rel err ~1e-6
        u64 gE = mul2(r, wI);              // 1/wE = sigma_E
        u64 gI = mul2(r, wE);              // 1/wI = sigma_I
        E2[p] = fma2(C01, gE, mul2(ME, E2[p]));
        I2[p] = fma2(KI,  gI, mul2(MI, I2[p]));
    };

    // pair 0: always tanh. pair 1: exp on 2 of every 5 steps (d=0.4).
    int b5  = steps / 5;
    int rem = steps - b5 * 5;
    for (int b = 0; b < b5; ++b) {
        tanh_step(0); tanh_step(1);
        tanh_step(0); tanh_step(1);
        tanh_step(0); exp_step(1);
        tanh_step(0); tanh_step(1);
        tanh_step(0); exp_step(1);
    }
    for (int s = 0; s < rem; ++s) {
        tanh_step(0); tanh_step(1);
    }

    float4 eo, io;
    unpack2(eo.x, eo.y, E2[0]); unpack2(eo.z, eo.w, E2[1]);
    unpack2(io.x, io.y, I2[0]); unpack2(io.z, io.w, I2[1]);
    eo.x = __saturatef(eo.x); eo.y = __saturatef(eo.y);
    eo.z = __saturatef(eo.z); eo.w = __saturatef(eo.w);
    io.x = __saturatef(io.x); io.y = __saturatef(io.y);
    io.z = __saturatef(io.z); io.w = __saturatef(io.w);

    reinterpret_cast<float4*>(out)[i]     = eo;
    reinterpret_cast<float4*>(out + n)[i] = io;
}

extern "C" void kernel_launch(void* const* d_in, const int* in_sizes, int n_in,
                              void* d_out, int out_size)
{
    const float4* E0    = (const float4*)d_in[0];
    const float4* I0    = (const float4*)d_in[1];
    const float4* IextE = (const float4*)d_in[2];
    const float4* IextI = (const float4*)d_in[3];
    const int* steps_ptr = (n_in >= 5) ? (const int*)d_in[4] : nullptr;

    int n = in_sizes[0];
    int n4 = n / 4;                     // 4 elems per thread = 1 float4
    int threads = 128;
    int blocks = (n4 + threads - 1) / threads;   // 2048

    wilson_cowan_kernel<<<blocks, threads>>>(E0, I0, IextE, IextI, steps_ptr,
                                             (float*)d_out, n, n4, out_size);
}